// round 5
// baseline (speedup 1.0000x reference)
#include <cuda_runtime.h>
#include <math.h>

// ---------------- problem constants ----------------
#define NCLS   80
#define NTGT   512
#define NA     3
#define NOFF   5
#define NB     16

#define HW0    6400   // 80x80
#define HW1    1600   // 40x40
#define HW2    400    // 20x20
#define CELLS0 (NB*NA*HW0)   // 307200
#define CELLS1 (NB*NA*HW1)   // 76800
#define CELLS2 (NB*NA*HW2)   // 19200
#define CELLS_TOTAL (CELLS0+CELLS1+CELLS2)  // 403200

#define ENTRIES_PER_LEVEL (NOFF*NA*NTGT)        // 7680
#define ENTRIES_TOTAL     (3*ENTRIES_PER_LEVEL) // 23040

#define OBJ_BLOCKS   (CELLS_TOTAL/256)   // 1575
#define ENTRY_BLOCKS (ENTRIES_TOTAL/8)   // 2880 (8 warps/block)

// ---------------- persistent scratch (zero-initialized at load) ----------------
__device__ float  g_objgt[CELLS_TOTAL];          // stays all-zero between calls (invariant)
__device__ int    g_list[ENTRIES_TOTAL];         // touched-cell list (global objgt indices)
__device__ int    g_nlist;                       // list length
// per level: [box_sum, cnt, cls_sum, obj_softplus_sum]
__device__ double g_acc[12];

__constant__ float c_anchors[3][NA][2] = {
    {{10.f,13.f},{16.f,30.f},{33.f,23.f}},
    {{30.f,61.f},{62.f,45.f},{59.f,119.f}},
    {{116.f,90.f},{156.f,198.f},{373.f,326.f}}
};
__constant__ float c_offx[NOFF] = {0.f, 0.5f, 0.f, -0.5f, 0.f};
__constant__ float c_offy[NOFF] = {0.f, 0.f, 0.5f, 0.f, -0.5f};

__device__ __forceinline__ float bce_logits(float x, float z) {
    return fmaxf(x, 0.f) - x * z + log1pf(expf(-fabsf(x)));
}
__device__ __forceinline__ float softplusf_(float x) {       // bce(x, 0)
    return fmaxf(x, 0.f) + log1pf(expf(-fabsf(x)));
}
__device__ __forceinline__ float sigmoidf_(float x) {
    return 1.f / (1.f + expf(-x));
}

// ============ kernel A: fused entry (box/cls/scatter) + obj softplus sum ============
__global__ void yolo_main_kernel(const float* __restrict__ p0,
                                 const float* __restrict__ p1,
                                 const float* __restrict__ p2,
                                 const float* __restrict__ tgt) {
    if (blockIdx.x < OBJ_BLOCKS) {
        // ---- objectness part: Σ softplus(obj_logit), target-independent ----
        __shared__ float s_part[8];
        int i = blockIdx.x * 256 + threadIdx.x;
        int level, cell, HW;
        const float* layer;
        if (i < CELLS0)               { level = 0; cell = i;                   HW = HW0; layer = p0; }
        else if (i < CELLS0 + CELLS1) { level = 1; cell = i - CELLS0;          HW = HW1; layer = p1; }
        else                          { level = 2; cell = i - CELLS0 - CELLS1; HW = HW2; layer = p2; }

        int b  = cell / (NA * HW);
        int r  = cell % (NA * HW);
        int a  = r / HW;
        int hw = r % HW;
        float v = softplusf_(layer[(b * 255 + a * 85 + 4) * HW + hw]);

        #pragma unroll
        for (int s = 16; s > 0; s >>= 1)
            v += __shfl_xor_sync(0xffffffffu, v, s);
        int lane = threadIdx.x & 31;
        int warp = threadIdx.x >> 5;
        if (lane == 0) s_part[warp] = v;
        __syncthreads();
        if (warp == 0) {
            float bsum = (lane < 8) ? s_part[lane] : 0.f;
            #pragma unroll
            for (int s = 4; s > 0; s >>= 1)
                bsum += __shfl_xor_sync(0xffffffffu, bsum, s);
            if (lane == 0)
                atomicAdd(&g_acc[level * 4 + 3], (double)bsum);
        }
        return;
    }

    // ---- entry part: one warp per (level, offset, anchor, target) ----
    int gwid = (blockIdx.x - OBJ_BLOCKS) * 8 + (threadIdx.x >> 5);
    int lane = threadIdx.x & 31;

    int level = gwid / ENTRIES_PER_LEVEL;
    int e     = gwid % ENTRIES_PER_LEVEL;
    int o = e / (NA * NTGT);
    int a = (e / NTGT) % NA;
    int n = e % NTGT;

    int Wd, HW, scoff;
    const float* layer;
    if (level == 0)      { Wd = 80; HW = HW0; scoff = 0;               layer = p0; }
    else if (level == 1) { Wd = 40; HW = HW1; scoff = CELLS0;          layer = p1; }
    else                 { Wd = 20; HW = HW2; scoff = CELLS0 + CELLS1; layer = p2; }
    float Wf = (float)Wd;

    const float* t = tgt + n * 6;
    float tx = t[2] * Wf;
    float ty = t[3] * Wf;
    float tw = t[4] * Wf;
    float th = t[5] * Wf;

    float aw = c_anchors[level][a][0];
    float ah = c_anchors[level][a][1];

    float rw = tw / aw, rh = th / ah;
    float m = fmaxf(fmaxf(rw, 1.f / rw), fmaxf(rh, 1.f / rh));
    bool sel = (m < 4.0f);

    float xmod = fmodf(tx, 1.0f);
    float ymod = fmodf(ty, 1.0f);
    bool cond;
    switch (o) {
        case 0: cond = true; break;
        case 1: cond = (xmod < 0.5f) && (tx > 1.0f); break;
        case 2: cond = (ymod < 0.5f) && (ty > 1.0f); break;
        case 3: cond = (xmod > 0.5f) && (tx < Wf - 1.0f); break;
        default: cond = (ymod > 0.5f) && (ty < Wf - 1.0f); break;
    }
    if (!(sel && cond)) return;   // warp-uniform

    int grid_x = (int)(tx - c_offx[o]);
    int grid_y = (int)(ty - c_offy[o]);
    float gxyx = tx - (float)grid_x;   // unclipped grid (matches ref)
    float gxyy = ty - (float)grid_y;
    int gx = min(max(grid_x, 0), Wd - 1);
    int gy = min(max(grid_y, 0), Wd - 1);

    int im = (int)t[0];
    int ci = (int)t[1];

    int base = ((im * 255 + a * 85) * HW) + gy * Wd + gx;

    // class loss: lanes split 80 channels
    float csum = 0.f;
    for (int j = lane; j < NCLS; j += 32) {
        float x = layer[base + (5 + j) * HW];
        csum += bce_logits(x, (j == ci) ? 1.0f : 0.0f);
    }
    #pragma unroll
    for (int s = 16; s > 0; s >>= 1)
        csum += __shfl_xor_sync(0xffffffffu, csum, s);

    if (lane == 0) {
        float op0 = layer[base];
        float op1 = layer[base + HW];
        float op2 = layer[base + 2 * HW];
        float op3 = layer[base + 3 * HW];

        float px = sigmoidf_(op0) * 2.0f - 0.5f;
        float py = sigmoidf_(op1) * 2.0f - 0.5f;
        float sw = sigmoidf_(op2) * 2.0f;
        float sh = sigmoidf_(op3) * 2.0f;
        float pw = sw * sw * aw;
        float ph = sh * sh * ah;

        float ax0 = px - pw * 0.5f, ax1 = px + pw * 0.5f;
        float ay0 = py - ph * 0.5f, ay1 = py + ph * 0.5f;
        float bx0 = gxyx - tw * 0.5f, bx1 = gxyx + tw * 0.5f;
        float by0 = gxyy - th * 0.5f, by1 = gxyy + th * 0.5f;
        float iw = fmaxf(fminf(ax1, bx1) - fmaxf(ax0, bx0), 0.0f);
        float ih = fmaxf(fminf(ay1, by1) - fmaxf(ay0, by0), 0.0f);
        float inter = iw * ih;
        float uni = (ax1 - ax0) * (ay1 - ay0) + (bx1 - bx0) * (by1 - by0) - inter;
        float iou = inter / uni;
        float cw = fmaxf(ax1, bx1) - fminf(ax0, bx0) + 1e-16f;
        float ch = fmaxf(ay1, by1) - fminf(ay0, by0);
        float carea = cw * ch + 1e-16f;
        float giou = iou - (carea - uni) / carea;

        atomicAdd(&g_acc[level * 4 + 0], (double)(1.0f - giou));
        atomicAdd(&g_acc[level * 4 + 1], 1.0);
        atomicAdd(&g_acc[level * 4 + 2], (double)csum);

        // scatter clip(giou,0) with uint-bit max dedup; record touched cell
        float gval = fmaxf(giou, 0.0f);
        int sc = scoff + (im * NA + a) * HW + gy * Wd + gx;
        atomicMax((unsigned int*)&g_objgt[sc], __float_as_uint(gval));
        int slot = atomicAdd(&g_nlist, 1);
        g_list[slot] = sc;
    }
}

// ============ kernel B: sparse obj corrections + finalize + state cleanup ============
// single block, 1024 threads
__global__ void yolo_final_kernel(const float* __restrict__ p0,
                                  const float* __restrict__ p1,
                                  const float* __restrict__ p2,
                                  float* __restrict__ out) {
    __shared__ double s_corr[3];
    if (threadIdx.x < 3) s_corr[threadIdx.x] = 0.0;
    __syncthreads();

    int nlist = g_nlist;
    double corr0 = 0.0, corr1 = 0.0, corr2 = 0.0;

    for (int i = threadIdx.x; i < nlist; i += 1024) {
        int c = g_list[i];
        // first visitor gets the deduped max giou AND clears the cell for next replay;
        // duplicate visitors get 0 -> zero correction.
        float g = __uint_as_float(atomicExch((unsigned int*)&g_objgt[c], 0u));
        if (g != 0.0f) {
            int level, local, HW;
            const float* layer;
            if (c < CELLS0)               { level = 0; local = c;                   HW = HW0; layer = p0; }
            else if (c < CELLS0 + CELLS1) { level = 1; local = c - CELLS0;          HW = HW1; layer = p1; }
            else                          { level = 2; local = c - CELLS0 - CELLS1; HW = HW2; layer = p2; }
            int b  = local / (NA * HW);
            int r  = local % (NA * HW);
            int a  = r / HW;
            int hw = r % HW;
            float x = layer[(b * 255 + a * 85 + 4) * HW + hw];
            // bce(x,g) - bce(x,0) = -x*g
            double d = -(double)x * (double)g;
            if (level == 0) corr0 += d; else if (level == 1) corr1 += d; else corr2 += d;
        }
    }

    // warp reduce, then shared atomics (one per warp per level)
    #pragma unroll
    for (int s = 16; s > 0; s >>= 1) {
        corr0 += __shfl_xor_sync(0xffffffffu, corr0, s);
        corr1 += __shfl_xor_sync(0xffffffffu, corr1, s);
        corr2 += __shfl_xor_sync(0xffffffffu, corr2, s);
    }
    if ((threadIdx.x & 31) == 0) {
        atomicAdd(&s_corr[0], corr0);
        atomicAdd(&s_corr[1], corr1);
        atomicAdd(&s_corr[2], corr2);
    }
    __syncthreads();

    if (threadIdx.x == 0) {
        const double bal[3]   = {4.0, 1.0, 0.4};
        const double cells[3] = {(double)CELLS0, (double)CELLS1, (double)CELLS2};
        double lbox = 0.0, lobj = 0.0, lcls = 0.0;
        for (int l = 0; l < 3; l++) {
            double cnt = g_acc[l * 4 + 1];
            if (cnt > 0.0) {
                lbox += g_acc[l * 4 + 0] / cnt;
                lcls += g_acc[l * 4 + 2] / (cnt * (double)NCLS);
            }
            lobj += bal[l] * ((g_acc[l * 4 + 3] + s_corr[l]) / cells[l]);
        }
        double loss = (0.05 * lbox + 1.0 * lobj + 0.5 * lcls) * (double)NB;
        out[0] = (float)loss;

        // reset state for next replay
        for (int i = 0; i < 12; i++) g_acc[i] = 0.0;
        g_nlist = 0;
    }
}

// ---------------- launch ----------------
extern "C" void kernel_launch(void* const* d_in, const int* in_sizes, int n_in,
                              void* d_out, int out_size) {
    const float* p0  = (const float*)d_in[0];
    const float* p1  = (const float*)d_in[1];
    const float* p2  = (const float*)d_in[2];
    const float* tgt = (const float*)d_in[3];
    float* out = (float*)d_out;

    yolo_main_kernel<<<OBJ_BLOCKS + ENTRY_BLOCKS, 256>>>(p0, p1, p2, tgt);
    yolo_final_kernel<<<1, 1024>>>(p0, p1, p2, out);
}

// round 6
// speedup vs baseline: 1.2532x; 1.2532x over previous
#include <cuda_runtime.h>
#include <math.h>

// ---------------- problem constants ----------------
#define NCLS   80
#define NTGT   512
#define NA     3
#define NOFF   5
#define NB     16

#define HW0    6400   // 80x80
#define HW1    1600   // 40x40
#define HW2    400    // 20x20
#define CELLS0 (NB*NA*HW0)   // 307200
#define CELLS1 (NB*NA*HW1)   // 76800
#define CELLS2 (NB*NA*HW2)   // 19200
#define CELLS_TOTAL (CELLS0+CELLS1+CELLS2)  // 403200

#define ENTRIES_PER_LEVEL (NOFF*NA*NTGT)        // 7680
#define ENTRIES_TOTAL     (3*ENTRIES_PER_LEVEL) // 23040

#define OBJ_BLOCKS   (CELLS_TOTAL/256)   // 1575
#define ENTRY_BLOCKS (ENTRIES_TOTAL/8)   // 2880 (8 warps of 32 per block)
#define TOTAL_BLOCKS (OBJ_BLOCKS + ENTRY_BLOCKS)

// ---------------- persistent scratch (zero-init at load; kernel restores zeros) ----
// per level: [box_sum, cnt, cls_sum, obj_sum(softplus - x*g)]
__device__ double       g_acc[12];
__device__ unsigned int g_done;   // completed-block ticket counter

__constant__ float c_anchors[3][NA][2] = {
    {{10.f,13.f},{16.f,30.f},{33.f,23.f}},
    {{30.f,61.f},{62.f,45.f},{59.f,119.f}},
    {{116.f,90.f},{156.f,198.f},{373.f,326.f}}
};
__constant__ float c_offx[NOFF] = {0.f, 0.5f, 0.f, -0.5f, 0.f};
__constant__ float c_offy[NOFF] = {0.f, 0.f, 0.5f, 0.f, -0.5f};

__device__ __forceinline__ float bce_logits(float x, float z) {
    return fmaxf(x, 0.f) - x * z + log1pf(expf(-fabsf(x)));
}
__device__ __forceinline__ float softplusf_(float x) {       // bce(x, 0)
    return fmaxf(x, 0.f) + log1pf(expf(-fabsf(x)));
}
__device__ __forceinline__ float sigmoidf_(float x) {
    return 1.f / (1.f + expf(-x));
}

// ================= single fused kernel =================
__global__ void __launch_bounds__(256)
yolo_fused_kernel(const float* __restrict__ p0,
                  const float* __restrict__ p1,
                  const float* __restrict__ p2,
                  const float* __restrict__ tgt,
                  float* __restrict__ out) {
    if (blockIdx.x < OBJ_BLOCKS) {
        // ---- dense objectness: Σ softplus(obj_logit). Coalesced. ----
        __shared__ float s_part[8];
        int i = blockIdx.x * 256 + threadIdx.x;
        int level, cell, HW;
        const float* layer;
        if (i < CELLS0)               { level = 0; cell = i;                   HW = HW0; layer = p0; }
        else if (i < CELLS0 + CELLS1) { level = 1; cell = i - CELLS0;          HW = HW1; layer = p1; }
        else                          { level = 2; cell = i - CELLS0 - CELLS1; HW = HW2; layer = p2; }

        int b  = cell / (NA * HW);
        int r  = cell % (NA * HW);
        int a  = r / HW;
        int hw = r % HW;
        float v = softplusf_(layer[(b * 255 + a * 85 + 4) * HW + hw]);

        #pragma unroll
        for (int s = 16; s > 0; s >>= 1)
            v += __shfl_xor_sync(0xffffffffu, v, s);
        int lane = threadIdx.x & 31;
        int warp = threadIdx.x >> 5;
        if (lane == 0) s_part[warp] = v;
        __syncthreads();
        if (warp == 0) {
            float bsum = (lane < 8) ? s_part[lane] : 0.f;
            #pragma unroll
            for (int s = 4; s > 0; s >>= 1)
                bsum += __shfl_xor_sync(0xffffffffu, bsum, s);
            if (lane == 0)
                atomicAdd(&g_acc[level * 4 + 3], (double)bsum);
        }
    } else {
        // ---- entry part: one warp per (level, offset, anchor, target) ----
        int gwid = (blockIdx.x - OBJ_BLOCKS) * 8 + (threadIdx.x >> 5);
        int lane = threadIdx.x & 31;

        int level = gwid / ENTRIES_PER_LEVEL;
        int e     = gwid % ENTRIES_PER_LEVEL;
        int o = e / (NA * NTGT);
        int a = (e / NTGT) % NA;
        int n = e % NTGT;

        int Wd, HW;
        const float* layer;
        if (level == 0)      { Wd = 80; HW = HW0; layer = p0; }
        else if (level == 1) { Wd = 40; HW = HW1; layer = p1; }
        else                 { Wd = 20; HW = HW2; layer = p2; }
        float Wf = (float)Wd;

        const float* t = tgt + n * 6;
        float tx = t[2] * Wf;
        float ty = t[3] * Wf;
        float tw = t[4] * Wf;
        float th = t[5] * Wf;

        float aw = c_anchors[level][a][0];
        float ah = c_anchors[level][a][1];

        float rw = tw / aw, rh = th / ah;
        float m = fmaxf(fmaxf(rw, 1.f / rw), fmaxf(rh, 1.f / rh));
        bool sel = (m < 4.0f);

        float xmod = fmodf(tx, 1.0f);
        float ymod = fmodf(ty, 1.0f);
        bool cond;
        switch (o) {
            case 0: cond = true; break;
            case 1: cond = (xmod < 0.5f) && (tx > 1.0f); break;
            case 2: cond = (ymod < 0.5f) && (ty > 1.0f); break;
            case 3: cond = (xmod > 0.5f) && (tx < Wf - 1.0f); break;
            default: cond = (ymod > 0.5f) && (ty < Wf - 1.0f); break;
        }

        if (sel && cond) {   // warp-uniform
            int grid_x = (int)(tx - c_offx[o]);
            int grid_y = (int)(ty - c_offy[o]);
            float gxyx = tx - (float)grid_x;   // unclipped grid (matches ref)
            float gxyy = ty - (float)grid_y;
            int gx = min(max(grid_x, 0), Wd - 1);
            int gy = min(max(grid_y, 0), Wd - 1);

            int im = (int)t[0];
            int ci = (int)t[1];

            int base = ((im * 255 + a * 85) * HW) + gy * Wd + gx;

            // class loss: lanes split 80 channels
            float csum = 0.f;
            for (int j = lane; j < NCLS; j += 32) {
                float x = layer[base + (5 + j) * HW];
                csum += bce_logits(x, (j == ci) ? 1.0f : 0.0f);
            }
            #pragma unroll
            for (int s = 16; s > 0; s >>= 1)
                csum += __shfl_xor_sync(0xffffffffu, csum, s);

            if (lane == 0) {
                float op0 = layer[base];
                float op1 = layer[base + HW];
                float op2 = layer[base + 2 * HW];
                float op3 = layer[base + 3 * HW];
                float opo = layer[base + 4 * HW];   // obj logit

                float px = sigmoidf_(op0) * 2.0f - 0.5f;
                float py = sigmoidf_(op1) * 2.0f - 0.5f;
                float sw = sigmoidf_(op2) * 2.0f;
                float sh = sigmoidf_(op3) * 2.0f;
                float pw = sw * sw * aw;
                float ph = sh * sh * ah;

                float ax0 = px - pw * 0.5f, ax1 = px + pw * 0.5f;
                float ay0 = py - ph * 0.5f, ay1 = py + ph * 0.5f;
                float bx0 = gxyx - tw * 0.5f, bx1 = gxyx + tw * 0.5f;
                float by0 = gxyy - th * 0.5f, by1 = gxyy + th * 0.5f;
                float iw = fmaxf(fminf(ax1, bx1) - fmaxf(ax0, bx0), 0.0f);
                float ih = fmaxf(fminf(ay1, by1) - fmaxf(ay0, by0), 0.0f);
                float inter = iw * ih;
                float uni = (ax1 - ax0) * (ay1 - ay0) + (bx1 - bx0) * (by1 - by0) - inter;
                float iou = inter / uni;
                float cw = fmaxf(ax1, bx1) - fminf(ax0, bx0) + 1e-16f;
                float ch = fmaxf(ay1, by1) - fminf(ay0, by0);
                float carea = cw * ch + 1e-16f;
                float giou = iou - (carea - uni) / carea;

                // obj correction: bce(x,g) - bce(x,0) = -x*g  (g = clip(giou,0))
                float gval = fmaxf(giou, 0.0f);

                atomicAdd(&g_acc[level * 4 + 0], (double)(1.0f - giou));
                atomicAdd(&g_acc[level * 4 + 1], 1.0);
                atomicAdd(&g_acc[level * 4 + 2], (double)csum);
                atomicAdd(&g_acc[level * 4 + 3], -(double)opo * (double)gval);
            }
        }
        __syncthreads();  // re-converge entry block before ticket
    }

    // ---- last-block ticket: finalize + reset ----
    if (threadIdx.x == 0) {
        __threadfence();
        unsigned int ticket = atomicAdd(&g_done, 1u);
        if (ticket == (unsigned int)(TOTAL_BLOCKS - 1)) {
            volatile double* acc = g_acc;
            const double bal[3]   = {4.0, 1.0, 0.4};
            const double cells[3] = {(double)CELLS0, (double)CELLS1, (double)CELLS2};
            double lbox = 0.0, lobj = 0.0, lcls = 0.0;
            for (int l = 0; l < 3; l++) {
                double cnt = acc[l * 4 + 1];
                if (cnt > 0.0) {
                    lbox += acc[l * 4 + 0] / cnt;
                    lcls += acc[l * 4 + 2] / (cnt * (double)NCLS);
                }
                lobj += bal[l] * (acc[l * 4 + 3] / cells[l]);
            }
            // BOX_W=0.05, OBJ_W=1.0, CLS_W=0.5, scale=1, batch=16
            double loss = (0.05 * lbox + 1.0 * lobj + 0.5 * lcls) * (double)NB;
            out[0] = (float)loss;

            // reset state for next graph replay
            for (int i = 0; i < 12; i++) g_acc[i] = 0.0;
            g_done = 0u;
        }
    }
}

// ---------------- launch ----------------
extern "C" void kernel_launch(void* const* d_in, const int* in_sizes, int n_in,
                              void* d_out, int out_size) {
    const float* p0  = (const float*)d_in[0];
    const float* p1  = (const float*)d_in[1];
    const float* p2  = (const float*)d_in[2];
    const float* tgt = (const float*)d_in[3];
    float* out = (float*)d_out;

    yolo_fused_kernel<<<TOTAL_BLOCKS, 256>>>(p0, p1, p2, tgt, out);
}

// round 7
// speedup vs baseline: 2.4375x; 1.9451x over previous
#include <cuda_runtime.h>
#include <math.h>

// ---------------- problem constants ----------------
#define NCLS   80
#define NTGT   512
#define NA     3
#define NOFF   5
#define NB     16

#define HW0    6400   // 80x80
#define HW1    1600   // 40x40
#define HW2    400    // 20x20
#define CELLS0 (NB*NA*HW0)   // 307200
#define CELLS1 (NB*NA*HW1)   // 76800
#define CELLS2 (NB*NA*HW2)   // 19200
#define CELLS_TOTAL (CELLS0+CELLS1+CELLS2)  // 403200

#define ENTRIES_PER_LEVEL (NOFF*NA*NTGT)        // 7680
#define ENTRIES_TOTAL     (3*ENTRIES_PER_LEVEL) // 23040

// dense obj pass in float4 units
#define OBJ4_0      (CELLS0/4)          // 76800
#define OBJ4_01     ((CELLS0+CELLS1)/4) // 96000
#define OBJ4_TOTAL  (CELLS_TOTAL/4)     // 100800
#define OBJ_BLOCKS  ((OBJ4_TOTAL + 255)/256)  // 394
#define ENTRY_BLOCKS (ENTRIES_TOTAL/8)        // 2880 (8 warps/block)
#define TOTAL_BLOCKS (OBJ_BLOCKS + ENTRY_BLOCKS)

// ---------------- persistent scratch (zero-init at load; kernel restores zeros) ----
// per level: [box_sum, cnt, cls_sum, obj_sum(softplus - x*g)]
__device__ double       g_acc[12];
__device__ unsigned int g_done;

__constant__ float c_anchors[3][NA][2] = {
    {{10.f,13.f},{16.f,30.f},{33.f,23.f}},
    {{30.f,61.f},{62.f,45.f},{59.f,119.f}},
    {{116.f,90.f},{156.f,198.f},{373.f,326.f}}
};
__constant__ float c_offx[NOFF] = {0.f, 0.5f, 0.f, -0.5f, 0.f};
__constant__ float c_offy[NOFF] = {0.f, 0.f, 0.5f, 0.f, -0.5f};

__device__ __forceinline__ float softplus_fast(float x) {    // bce(x, 0)
    return fmaxf(x, 0.f) + __logf(1.0f + __expf(-fabsf(x)));
}
__device__ __forceinline__ float bce_fast(float x, float z) {
    return fmaxf(x, 0.f) - x * z + __logf(1.0f + __expf(-fabsf(x)));
}
__device__ __forceinline__ float sigmoidf_(float x) {
    return 1.f / (1.f + __expf(-x));
}

// ================= single fused kernel =================
__global__ void __launch_bounds__(256)
yolo_fused_kernel(const float* __restrict__ p0,
                  const float* __restrict__ p1,
                  const float* __restrict__ p2,
                  const float* __restrict__ tgt,
                  float* __restrict__ out) {
    if (blockIdx.x < OBJ_BLOCKS) {
        // ---- dense objectness: Σ softplus(obj_logit), float4-vectorized ----
        __shared__ float s_part[8];
        int i4 = blockIdx.x * 256 + threadIdx.x;
        float s = 0.f;
        if (i4 < OBJ4_TOTAL) {
            int cell4, HW4;
            const float* layer;
            if (i4 < OBJ4_0)       { cell4 = i4;           HW4 = HW0/4; layer = p0; }
            else if (i4 < OBJ4_01) { cell4 = i4 - OBJ4_0;  HW4 = HW1/4; layer = p1; }
            else                   { cell4 = i4 - OBJ4_01; HW4 = HW2/4; layer = p2; }
            int b   = cell4 / (NA * HW4);
            int r   = cell4 % (NA * HW4);
            int a   = r / HW4;
            int hw4 = r % HW4;
            const float4* ptr = (const float4*)(layer) + (size_t)(b * 255 + a * 85 + 4) * HW4 + hw4;
            float4 v = *ptr;
            s = softplus_fast(v.x) + softplus_fast(v.y) + softplus_fast(v.z) + softplus_fast(v.w);
        }
        #pragma unroll
        for (int sh = 16; sh > 0; sh >>= 1)
            s += __shfl_xor_sync(0xffffffffu, s, sh);
        int lane = threadIdx.x & 31;
        int warp = threadIdx.x >> 5;
        if (lane == 0) s_part[warp] = s;
        __syncthreads();
        if (warp == 0) {
            float bsum = (lane < 8) ? s_part[lane] : 0.f;
            #pragma unroll
            for (int sh = 4; sh > 0; sh >>= 1)
                bsum += __shfl_xor_sync(0xffffffffu, bsum, sh);
            if (lane == 0) {
                // level per block: boundaries 300 / 375 are exact block indices
                int level = (blockIdx.x < OBJ4_0/256) ? 0 : ((blockIdx.x < OBJ4_01/256) ? 1 : 2);
                atomicAdd(&g_acc[level * 4 + 3], (double)bsum);
            }
        }
    } else {
        // ---- entry part: one warp per (level, offset, anchor, target); level-pure blocks ----
        __shared__ double s_acc[4];   // box, cnt, cls, obj-corr
        if (threadIdx.x < 4) s_acc[threadIdx.x] = 0.0;
        __syncthreads();

        int gwid = (blockIdx.x - OBJ_BLOCKS) * 8 + (threadIdx.x >> 5);
        int lane = threadIdx.x & 31;

        int level = gwid / ENTRIES_PER_LEVEL;
        int e     = gwid % ENTRIES_PER_LEVEL;
        int o = e / (NA * NTGT);
        int a = (e / NTGT) % NA;
        int n = e % NTGT;

        int Wd, HW;
        const float* layer;
        if (level == 0)      { Wd = 80; HW = HW0; layer = p0; }
        else if (level == 1) { Wd = 40; HW = HW1; layer = p1; }
        else                 { Wd = 20; HW = HW2; layer = p2; }
        float Wf = (float)Wd;

        const float* t = tgt + n * 6;
        float tx = t[2] * Wf;
        float ty = t[3] * Wf;
        float tw = t[4] * Wf;
        float th = t[5] * Wf;

        float aw = c_anchors[level][a][0];
        float ah = c_anchors[level][a][1];

        float rw = tw / aw, rh = th / ah;
        float m = fmaxf(fmaxf(rw, 1.f / rw), fmaxf(rh, 1.f / rh));
        bool sel = (m < 4.0f);

        float xmod = fmodf(tx, 1.0f);
        float ymod = fmodf(ty, 1.0f);
        bool cond;
        switch (o) {
            case 0: cond = true; break;
            case 1: cond = (xmod < 0.5f) && (tx > 1.0f); break;
            case 2: cond = (ymod < 0.5f) && (ty > 1.0f); break;
            case 3: cond = (xmod > 0.5f) && (tx < Wf - 1.0f); break;
            default: cond = (ymod > 0.5f) && (ty < Wf - 1.0f); break;
        }

        if (sel && cond) {   // warp-uniform
            int grid_x = (int)(tx - c_offx[o]);
            int grid_y = (int)(ty - c_offy[o]);
            float gxyx = tx - (float)grid_x;   // unclipped grid (matches ref)
            float gxyy = ty - (float)grid_y;
            int gx = min(max(grid_x, 0), Wd - 1);
            int gy = min(max(grid_y, 0), Wd - 1);

            int im = (int)t[0];
            int ci = (int)t[1];

            const float* cellp = layer + (size_t)((im * 255 + a * 85) * HW) + gy * Wd + gx;

            // ---- one-shot load phase: 85 channels via 3 independent LDGs ----
            float xk0 = cellp[(size_t)lane * HW];                 // channels 0..31
            float xk1 = cellp[(size_t)(lane + 32) * HW];          // channels 32..63
            float xk2 = (lane < 21) ? cellp[(size_t)(lane + 64) * HW] : 0.f; // 64..84

            // class bce: class index = channel - 5
            float csum = 0.f;
            if (lane >= 5) csum += bce_fast(xk0, (lane - 5 == ci) ? 1.0f : 0.0f);
            csum += bce_fast(xk1, (lane + 27 == ci) ? 1.0f : 0.0f);
            if (lane < 21) csum += bce_fast(xk2, (lane + 59 == ci) ? 1.0f : 0.0f);

            // broadcast box/obj logits (channels 0..4 live in lanes 0..4 of xk0)
            float op0 = __shfl_sync(0xffffffffu, xk0, 0);
            float op1 = __shfl_sync(0xffffffffu, xk0, 1);
            float op2 = __shfl_sync(0xffffffffu, xk0, 2);
            float op3 = __shfl_sync(0xffffffffu, xk0, 3);
            float opo = __shfl_sync(0xffffffffu, xk0, 4);

            #pragma unroll
            for (int sh = 16; sh > 0; sh >>= 1)
                csum += __shfl_xor_sync(0xffffffffu, csum, sh);

            if (lane == 0) {
                float px = sigmoidf_(op0) * 2.0f - 0.5f;
                float py = sigmoidf_(op1) * 2.0f - 0.5f;
                float sw = sigmoidf_(op2) * 2.0f;
                float sh2 = sigmoidf_(op3) * 2.0f;
                float pw = sw * sw * aw;
                float ph = sh2 * sh2 * ah;

                float ax0 = px - pw * 0.5f, ax1 = px + pw * 0.5f;
                float ay0 = py - ph * 0.5f, ay1 = py + ph * 0.5f;
                float bx0 = gxyx - tw * 0.5f, bx1 = gxyx + tw * 0.5f;
                float by0 = gxyy - th * 0.5f, by1 = gxyy + th * 0.5f;
                float iw = fmaxf(fminf(ax1, bx1) - fmaxf(ax0, bx0), 0.0f);
                float ih = fmaxf(fminf(ay1, by1) - fmaxf(ay0, by0), 0.0f);
                float inter = iw * ih;
                float uni = (ax1 - ax0) * (ay1 - ay0) + (bx1 - bx0) * (by1 - by0) - inter;
                float iou = inter / uni;
                float cw = fmaxf(ax1, bx1) - fminf(ax0, bx0) + 1e-16f;
                float ch = fmaxf(ay1, by1) - fminf(ay0, by0);
                float carea = cw * ch + 1e-16f;
                float giou = iou - (carea - uni) / carea;

                float gval = fmaxf(giou, 0.0f);

                atomicAdd(&s_acc[0], (double)(1.0f - giou));
                atomicAdd(&s_acc[1], 1.0);
                atomicAdd(&s_acc[2], (double)csum);
                atomicAdd(&s_acc[3], -(double)opo * (double)gval);  // bce(x,g)-bce(x,0) = -x*g
            }
        }
        __syncthreads();
        if (threadIdx.x == 0 && s_acc[1] != 0.0) {
            atomicAdd(&g_acc[level * 4 + 0], s_acc[0]);
            atomicAdd(&g_acc[level * 4 + 1], s_acc[1]);
            atomicAdd(&g_acc[level * 4 + 2], s_acc[2]);
            atomicAdd(&g_acc[level * 4 + 3], s_acc[3]);
        }
    }

    // ---- last-block ticket: finalize + reset ----
    if (threadIdx.x == 0) {
        __threadfence();
        unsigned int ticket = atomicAdd(&g_done, 1u);
        if (ticket == (unsigned int)(TOTAL_BLOCKS - 1)) {
            volatile double* acc = g_acc;
            const double bal[3]   = {4.0, 1.0, 0.4};
            const double cells[3] = {(double)CELLS0, (double)CELLS1, (double)CELLS2};
            double lbox = 0.0, lobj = 0.0, lcls = 0.0;
            for (int l = 0; l < 3; l++) {
                double cnt = acc[l * 4 + 1];
                if (cnt > 0.0) {
                    lbox += acc[l * 4 + 0] / cnt;
                    lcls += acc[l * 4 + 2] / (cnt * (double)NCLS);
                }
                lobj += bal[l] * (acc[l * 4 + 3] / cells[l]);
            }
            double loss = (0.05 * lbox + 1.0 * lobj + 0.5 * lcls) * (double)NB;
            out[0] = (float)loss;

            for (int i = 0; i < 12; i++) g_acc[i] = 0.0;
            g_done = 0u;
        }
    }
}

// ---------------- launch ----------------
extern "C" void kernel_launch(void* const* d_in, const int* in_sizes, int n_in,
                              void* d_out, int out_size) {
    const float* p0  = (const float*)d_in[0];
    const float* p1  = (const float*)d_in[1];
    const float* p2  = (const float*)d_in[2];
    const float* tgt = (const float*)d_in[3];
    float* out = (float*)d_out;

    yolo_fused_kernel<<<TOTAL_BLOCKS, 256>>>(p0, p1, p2, tgt, out);
}

// round 8
// speedup vs baseline: 2.7797x; 1.1404x over previous
#include <cuda_runtime.h>
#include <math.h>

// ---------------- problem constants ----------------
#define NCLS   80
#define NTGT   512
#define NA     3
#define NB     16

#define HW0    6400   // 80x80
#define HW1    1600   // 40x40
#define HW2    400    // 20x20
#define CELLS0 (NB*NA*HW0)   // 307200
#define CELLS1 (NB*NA*HW1)   // 76800
#define CELLS2 (NB*NA*HW2)   // 19200
#define CELLS_TOTAL (CELLS0+CELLS1+CELLS2)  // 403200

// one warp per (level, anchor, target)
#define PAIRS_PER_LEVEL (NA*NTGT)          // 1536
#define PAIRS_TOTAL     (3*PAIRS_PER_LEVEL) // 4608

// dense obj pass in float4 units
#define OBJ4_0      (CELLS0/4)          // 76800
#define OBJ4_01     ((CELLS0+CELLS1)/4) // 96000
#define OBJ4_TOTAL  (CELLS_TOTAL/4)     // 100800
#define OBJ_BLOCKS  ((OBJ4_TOTAL + 255)/256)  // 394
#define ENTRY_BLOCKS (PAIRS_TOTAL/8)          // 576 (8 warps/block, level-pure)
#define TOTAL_BLOCKS (OBJ_BLOCKS + ENTRY_BLOCKS)

// ---------------- persistent scratch (zero-init at load; kernel restores zeros) ----
// per level: [box_sum, cnt, cls_sum, obj_sum(softplus - x*g)]
__device__ double       g_acc[12];
__device__ unsigned int g_done;

__constant__ float c_anchors[3][NA][2] = {
    {{10.f,13.f},{16.f,30.f},{33.f,23.f}},
    {{30.f,61.f},{62.f,45.f},{59.f,119.f}},
    {{116.f,90.f},{156.f,198.f},{373.f,326.f}}
};

__device__ __forceinline__ float softplus_fast(float x) {    // bce(x, 0)
    return fmaxf(x, 0.f) + __logf(1.0f + __expf(-fabsf(x)));
}
__device__ __forceinline__ float bce_fast(float x, float z) {
    return fmaxf(x, 0.f) - x * z + __logf(1.0f + __expf(-fabsf(x)));
}
__device__ __forceinline__ float sigmoidf_(float x) {
    return 1.f / (1.f + __expf(-x));
}

// ================= single fused kernel =================
__global__ void __launch_bounds__(256)
yolo_fused_kernel(const float* __restrict__ p0,
                  const float* __restrict__ p1,
                  const float* __restrict__ p2,
                  const float* __restrict__ tgt,
                  float* __restrict__ out) {
    if (blockIdx.x < OBJ_BLOCKS) {
        // ---- dense objectness: Σ softplus(obj_logit), float4-vectorized ----
        __shared__ float s_part[8];
        int i4 = blockIdx.x * 256 + threadIdx.x;
        float s = 0.f;
        if (i4 < OBJ4_TOTAL) {
            int cell4, HW4;
            const float* layer;
            if (i4 < OBJ4_0)       { cell4 = i4;           HW4 = HW0/4; layer = p0; }
            else if (i4 < OBJ4_01) { cell4 = i4 - OBJ4_0;  HW4 = HW1/4; layer = p1; }
            else                   { cell4 = i4 - OBJ4_01; HW4 = HW2/4; layer = p2; }
            int b   = cell4 / (NA * HW4);
            int r   = cell4 % (NA * HW4);
            int a   = r / HW4;
            int hw4 = r % HW4;
            const float4* ptr = (const float4*)(layer) + (size_t)(b * 255 + a * 85 + 4) * HW4 + hw4;
            float4 v = *ptr;
            s = softplus_fast(v.x) + softplus_fast(v.y) + softplus_fast(v.z) + softplus_fast(v.w);
        }
        #pragma unroll
        for (int sh = 16; sh > 0; sh >>= 1)
            s += __shfl_xor_sync(0xffffffffu, s, sh);
        int lane = threadIdx.x & 31;
        int warp = threadIdx.x >> 5;
        if (lane == 0) s_part[warp] = s;
        __syncthreads();
        if (warp == 0) {
            float bsum = (lane < 8) ? s_part[lane] : 0.f;
            #pragma unroll
            for (int sh = 4; sh > 0; sh >>= 1)
                bsum += __shfl_xor_sync(0xffffffffu, bsum, sh);
            if (lane == 0) {
                int level = (blockIdx.x < OBJ4_0/256) ? 0 : ((blockIdx.x < OBJ4_01/256) ? 1 : 2);
                atomicAdd(&g_acc[level * 4 + 3], (double)bsum);
            }
        }
    } else {
        // ---- entry part: ONE warp per (level, anchor, target), up to 3 offset-slots ----
        __shared__ double s_acc[4];   // box, cnt, cls, obj-corr
        if (threadIdx.x < 4) s_acc[threadIdx.x] = 0.0;
        __syncthreads();

        int gwid = (blockIdx.x - OBJ_BLOCKS) * 8 + (threadIdx.x >> 5);
        int lane = threadIdx.x & 31;

        int level = gwid / PAIRS_PER_LEVEL;
        int rem   = gwid % PAIRS_PER_LEVEL;
        int a = rem / NTGT;
        int n = rem % NTGT;

        int Wd, HW;
        const float* layer;
        if (level == 0)      { Wd = 80; HW = HW0; layer = p0; }
        else if (level == 1) { Wd = 40; HW = HW1; layer = p1; }
        else                 { Wd = 20; HW = HW2; layer = p2; }
        float Wf = (float)Wd;

        const float* t = tgt + n * 6;
        float tx = t[2] * Wf;
        float ty = t[3] * Wf;
        float tw = t[4] * Wf;
        float th = t[5] * Wf;

        float aw = c_anchors[level][a][0];
        float ah = c_anchors[level][a][1];

        float rw = tw / aw, rh = th / ah;
        float m = fmaxf(fmaxf(rw, 1.f / rw), fmaxf(rh, 1.f / rh));

        if (m < 4.0f) {   // warp-uniform anchor-ratio selection
            int im = (int)t[0];
            int ci = (int)t[1];

            // resolve the ≤3 valid offset slots
            float xmod = fmodf(tx, 1.0f);
            float ymod = fmodf(ty, 1.0f);
            float offx_ = 0.f, offy_ = 0.f;
            bool hasx = false, hasy = false;
            if (xmod < 0.5f) { if (tx > 1.0f)      { hasx = true; offx_ =  0.5f; } }
            else             { if (tx < Wf - 1.0f) { hasx = true; offx_ = -0.5f; } }
            if (ymod < 0.5f) { if (ty > 1.0f)      { hasy = true; offy_ =  0.5f; } }
            else             { if (ty < Wf - 1.0f) { hasy = true; offy_ = -0.5f; } }

            bool  valid[3] = {true, hasx, hasy};
            float ofx[3]   = {0.f, offx_, 0.f};
            float ofy[3]   = {0.f, 0.f,  offy_};

            float gxyx[3], gxyy[3];
            const float* cellp[3];
            #pragma unroll
            for (int s = 0; s < 3; s++) {
                int grid_x = (int)(tx - ofx[s]);
                int grid_y = (int)(ty - ofy[s]);
                gxyx[s] = tx - (float)grid_x;   // unclipped grid (matches ref)
                gxyy[s] = ty - (float)grid_y;
                int gx = min(max(grid_x, 0), Wd - 1);
                int gy = min(max(grid_y, 0), Wd - 1);
                cellp[s] = layer + (size_t)((im * 255 + a * 85) * HW) + gy * Wd + gx;
            }

            // ---- issue ALL gather loads up front (MLP up to 9 per lane) ----
            float xk[3][3];
            #pragma unroll
            for (int s = 0; s < 3; s++) {
                if (valid[s]) {
                    xk[s][0] = cellp[s][(size_t)lane * HW];
                    xk[s][1] = cellp[s][(size_t)(lane + 32) * HW];
                    xk[s][2] = (lane < 21) ? cellp[s][(size_t)(lane + 64) * HW] : 0.f;
                }
            }

            // ---- class bce per slot, fused butterfly reduce ----
            float csum[3] = {0.f, 0.f, 0.f};
            #pragma unroll
            for (int s = 0; s < 3; s++) {
                if (valid[s]) {
                    float c = 0.f;
                    if (lane >= 5) c += bce_fast(xk[s][0], (lane - 5 == ci) ? 1.0f : 0.0f);
                    c += bce_fast(xk[s][1], (lane + 27 == ci) ? 1.0f : 0.0f);
                    if (lane < 21) c += bce_fast(xk[s][2], (lane + 59 == ci) ? 1.0f : 0.0f);
                    csum[s] = c;
                }
            }
            #pragma unroll
            for (int sh = 16; sh > 0; sh >>= 1) {
                csum[0] += __shfl_xor_sync(0xffffffffu, csum[0], sh);
                csum[1] += __shfl_xor_sync(0xffffffffu, csum[1], sh);
                csum[2] += __shfl_xor_sync(0xffffffffu, csum[2], sh);
            }

            // broadcast box/obj logits (channels 0..4 live in lanes 0..4 of xk[s][0])
            float op0[3], op1[3], op2[3], op3[3], opo[3];
            #pragma unroll
            for (int s = 0; s < 3; s++) {
                if (valid[s]) {   // warp-uniform guard
                    op0[s] = __shfl_sync(0xffffffffu, xk[s][0], 0);
                    op1[s] = __shfl_sync(0xffffffffu, xk[s][0], 1);
                    op2[s] = __shfl_sync(0xffffffffu, xk[s][0], 2);
                    op3[s] = __shfl_sync(0xffffffffu, xk[s][0], 3);
                    opo[s] = __shfl_sync(0xffffffffu, xk[s][0], 4);
                }
            }

            if (lane == 0) {
                double bsum = 0.0, clsum = 0.0, ocsum = 0.0;
                int cnt = 0;
                #pragma unroll
                for (int s = 0; s < 3; s++) {
                    if (valid[s]) {
                        float px = sigmoidf_(op0[s]) * 2.0f - 0.5f;
                        float py = sigmoidf_(op1[s]) * 2.0f - 0.5f;
                        float sw = sigmoidf_(op2[s]) * 2.0f;
                        float sh2 = sigmoidf_(op3[s]) * 2.0f;
                        float pw = sw * sw * aw;
                        float ph = sh2 * sh2 * ah;

                        float ax0 = px - pw * 0.5f, ax1 = px + pw * 0.5f;
                        float ay0 = py - ph * 0.5f, ay1 = py + ph * 0.5f;
                        float bx0 = gxyx[s] - tw * 0.5f, bx1 = gxyx[s] + tw * 0.5f;
                        float by0 = gxyy[s] - th * 0.5f, by1 = gxyy[s] + th * 0.5f;
                        float iw = fmaxf(fminf(ax1, bx1) - fmaxf(ax0, bx0), 0.0f);
                        float ih = fmaxf(fminf(ay1, by1) - fmaxf(ay0, by0), 0.0f);
                        float inter = iw * ih;
                        float uni = (ax1 - ax0) * (ay1 - ay0) + (bx1 - bx0) * (by1 - by0) - inter;
                        float iou = inter / uni;
                        float cw = fmaxf(ax1, bx1) - fminf(ax0, bx0) + 1e-16f;
                        float ch = fmaxf(ay1, by1) - fminf(ay0, by0);
                        float carea = cw * ch + 1e-16f;
                        float giou = iou - (carea - uni) / carea;

                        float gval = fmaxf(giou, 0.0f);
                        bsum  += (double)(1.0f - giou);
                        clsum += (double)csum[s];
                        ocsum += -(double)opo[s] * (double)gval; // bce(x,g)-bce(x,0)
                        cnt++;
                    }
                }
                atomicAdd(&s_acc[0], bsum);
                atomicAdd(&s_acc[1], (double)cnt);
                atomicAdd(&s_acc[2], clsum);
                atomicAdd(&s_acc[3], ocsum);
            }
        }
        __syncthreads();
        if (threadIdx.x == 0 && s_acc[1] != 0.0) {
            atomicAdd(&g_acc[level * 4 + 0], s_acc[0]);
            atomicAdd(&g_acc[level * 4 + 1], s_acc[1]);
            atomicAdd(&g_acc[level * 4 + 2], s_acc[2]);
            atomicAdd(&g_acc[level * 4 + 3], s_acc[3]);
        }
    }

    // ---- last-block ticket: finalize + reset ----
    if (threadIdx.x == 0) {
        __threadfence();
        unsigned int ticket = atomicAdd(&g_done, 1u);
        if (ticket == (unsigned int)(TOTAL_BLOCKS - 1)) {
            volatile double* acc = g_acc;
            const double bal[3]   = {4.0, 1.0, 0.4};
            const double cells[3] = {(double)CELLS0, (double)CELLS1, (double)CELLS2};
            double lbox = 0.0, lobj = 0.0, lcls = 0.0;
            for (int l = 0; l < 3; l++) {
                double cnt = acc[l * 4 + 1];
                if (cnt > 0.0) {
                    lbox += acc[l * 4 + 0] / cnt;
                    lcls += acc[l * 4 + 2] / (cnt * (double)NCLS);
                }
                lobj += bal[l] * (acc[l * 4 + 3] / cells[l]);
            }
            double loss = (0.05 * lbox + 1.0 * lobj + 0.5 * lcls) * (double)NB;
            out[0] = (float)loss;

            for (int i = 0; i < 12; i++) g_acc[i] = 0.0;
            g_done = 0u;
        }
    }
}

// ---------------- launch ----------------
extern "C" void kernel_launch(void* const* d_in, const int* in_sizes, int n_in,
                              void* d_out, int out_size) {
    const float* p0  = (const float*)d_in[0];
    const float* p1  = (const float*)d_in[1];
    const float* p2  = (const float*)d_in[2];
    const float* tgt = (const float*)d_in[3];
    float* out = (float*)d_out;

    yolo_fused_kernel<<<TOTAL_BLOCKS, 256>>>(p0, p1, p2, tgt, out);
}